// round 1
// baseline (speedup 1.0000x reference)
#include <cuda_runtime.h>
#include <math.h>

// Problem constants (fixed by the reference)
#define B_DIM 2
#define L_DIM 2048
#define V_DIM 32001
#define ROWS (B_DIM * L_DIM)

__device__ __forceinline__ float gumbel_noise(float u) {
    const float GEPS = 1e-6f;
    return GEPS - logf(GEPS + (1.0f - GEPS) * u);
}

// One block (256 threads) per row. Non-mask rows: x_new = x, rev_rate row stays
// zero (pre-zeroed by memset). Mask rows: full SEDD reverse-rate + gumbel argmax.
__global__ void euler_row_kernel(const float* __restrict__ outp,   // [B,L,V]
                                 const int* __restrict__ xt,       // [B,L]
                                 const float* __restrict__ t,      // [B]
                                 const float* __restrict__ step_p, // [1]
                                 const float* __restrict__ u,      // [B,L,V]
                                 float* __restrict__ x_new,        // [B*L]
                                 float* __restrict__ rev)          // [B,L,V]
{
    const int row = blockIdx.x;
    const int tid = threadIdx.x;
    const int mask_tok = V_DIM - 1;

    int x = xt[row];
    if (x == -1) x = mask_tok;

    if (x != mask_tok) {
        // rev_rate row is exactly zero; xt_prob/gnoise is positive only at v=x.
        if (tid == 0) x_new[row] = (float)x;
        return;
    }

    // ---- mask row: heavy path (statistically ~0-1 rows out of 4096) ----
    const int b = row / L_DIM;
    const float EPS = 1e-3f;
    const float step = *step_p;
    const float sigma = (1.0f - EPS) / (1.0f - (1.0f - EPS) * t[b]);

    const float* __restrict__ orow = outp + (long long)row * V_DIM;
    const float* __restrict__ urow = u    + (long long)row * V_DIM;
    float* __restrict__       rrow = rev  + (long long)row * V_DIM;

    float sum = 0.0f;
    float best_v = -INFINITY;
    int   best_i = V_DIM;   // larger than any real index

    for (int v = tid; v < V_DIM; v += blockDim.x) {
        if (v == mask_tok) continue;
        float s = expf(orow[v]);
        sum += s;
        float r = sigma * s;          // rev_rate off-diagonal
        rrow[v] = r;
        float g = gumbel_noise(urow[v]);
        float ratio = (step * r) / g; // xt_prob[v] = 0 + step*rev
        if (ratio > best_v || (ratio == best_v && v < best_i)) {
            best_v = ratio;
            best_i = v;
        }
    }

    __shared__ float s_sum[256];
    __shared__ float s_val[256];
    __shared__ int   s_idx[256];
    s_sum[tid] = sum;
    s_val[tid] = best_v;
    s_idx[tid] = best_i;
    __syncthreads();

    for (int off = 128; off > 0; off >>= 1) {
        if (tid < off) {
            s_sum[tid] += s_sum[tid + off];
            float ov = s_val[tid + off];
            int   oi = s_idx[tid + off];
            if (ov > s_val[tid] || (ov == s_val[tid] && oi < s_idx[tid])) {
                s_val[tid] = ov;
                s_idx[tid] = oi;
            }
        }
        __syncthreads();
    }

    if (tid == 0) {
        float total = s_sum[0];
        float rd = sigma * (-total);           // diagonal rev_rate
        rrow[mask_tok] = rd;
        float prob = 1.0f + step * rd;         // oh=1 at diagonal
        float g = gumbel_noise(urow[mask_tok]);
        float ratio = prob / g;
        int res = s_idx[0];
        float bv = s_val[0];
        // diagonal index is V-1 (largest), so on tie the off-diagonal wins
        if (ratio > bv) res = mask_tok;
        x_new[row] = (res == mask_tok) ? -1.0f : (float)res;
    }
}

extern "C" void kernel_launch(void* const* d_in, const int* in_sizes, int n_in,
                              void* d_out, int out_size) {
    const float* outp   = (const float*)d_in[0]; // [B,L,V] f32
    const int*   xt     = (const int*)  d_in[1]; // [B,L]   i32
    const float* t      = (const float*)d_in[2]; // [B]     f32
    const float* step_p = (const float*)d_in[3]; // scalar  f32
    const float* u      = (const float*)d_in[4]; // [B,L,V] f32

    float* x_new = (float*)d_out;                  // first B*L elements
    float* rev   = (float*)d_out + ROWS;           // then B*L*V elements

    // Zero the rev_rate region (all non-mask rows are exactly zero; mask rows
    // get overwritten by the row kernel). Write-only 524 MB — the dominant cost.
    cudaMemsetAsync(rev, 0, (size_t)ROWS * V_DIM * sizeof(float));

    euler_row_kernel<<<ROWS, 256>>>(outp, xt, t, step_p, u, x_new, rev);
}